// round 8
// baseline (speedup 1.0000x reference)
#include <cuda_runtime.h>
#include <stdint.h>

// x, y : (B=2, C=32, H=80, W=240) float32
// out  : (B=2, 64, 64, 80, 240) float32
//   out[b, c,    d, h, w] = x[b, c,    h, w]   * (w >= d)   c < 32
//   out[b, c,    d, h, w] = y[b, c-32, h, w-d] * (w >= d)   c >= 32
//
// One CTA = one (b, c, h) row; all 64 disparities for BOTH halves.
// Write-bandwidth-bound: 629 MB stores, 16 STG.128 per thread.
// All addressing is 32-bit (out has 39.3M elems < 2^31) to cut register
// pressure and allow 3 CTAs/SM.

#define Bn 2
#define Cn 32
#define Dn 64
#define Hn 80
#define Wn 240
#define W4 (Wn / 4)      // 60
#define HW (Hn * Wn)     // 19200
#define HW4 (HW / 4)     // 4800 float4 per disparity slice

// De-interleaved y row: ysm[j][i] = y_row[i*4 + j]; gather at linear idx ->
// ysm[idx&3][idx>>2]. Lane stride 4 in idx -> conflict-free banks.
#define YSM(idx) ysm[(idx) & 3][(idx) >> 2]

// block = (60, 8), grid = (Hn, Cn, Bn); min 3 CTAs/SM
__global__ __launch_bounds__(480, 3) void cost_volume_kernel(
    const float* __restrict__ x,
    const float* __restrict__ y,
    float* __restrict__ out)
{
    __shared__ float ysm[4][64];

    const unsigned tx = threadIdx.x;   // 0..59
    const unsigned ty = threadIdx.y;   // 0..7
    const unsigned h  = blockIdx.x;
    const unsigned c  = blockIdx.y;
    const unsigned b  = blockIdx.z;

    const unsigned row_in = ((b * Cn + c) * Hn + h) * Wn;   // < 4.9M, fits u32

    if (ty == 0) {
        float4 yv = reinterpret_cast<const float4*>(y + row_in)[tx];
        ysm[0][tx] = yv.x;
        ysm[1][tx] = yv.y;
        ysm[2][tx] = yv.z;
        ysm[3][tx] = yv.w;
    }
    const float4 xv = reinterpret_cast<const float4*>(x + row_in)[tx];
    __syncthreads();

    const int w  = (int)(tx * 4);
    const int d0 = (int)(ty * 8);

    // base offsets in float4 units (max ~9.8M, fits u32)
    const unsigned baseL4 = ((b * 2 * Cn + c) * Dn * Hn + h) * (unsigned)W4 + tx
                          + (unsigned)d0 * HW4;
    float4* oL = reinterpret_cast<float4*>(out) + baseL4;
    float4* oR = oL + (unsigned)(Cn * Dn) * HW4;

    // Sliding window: for disparity d the right window is y[w-d .. w+3-d];
    // consecutive d's overlap by 3 elements.
    const int i0 = w - d0;
    float r0 = (i0     >= 0) ? YSM(i0    ) : 0.0f;
    float r1 = (i0 + 1 >= 0) ? YSM(i0 + 1) : 0.0f;
    float r2 = (i0 + 2 >= 0) ? YSM(i0 + 2) : 0.0f;
    float r3 = (i0 + 3 >= 0) ? YSM(i0 + 3) : 0.0f;

#pragma unroll
    for (int k = 0; k < 8; ++k) {
        const int d = d0 + k;

        float4 l = xv;
        if (w     < d) l.x = 0.0f;
        if (w + 1 < d) l.y = 0.0f;
        if (w + 2 < d) l.z = 0.0f;
        if (w + 3 < d) l.w = 0.0f;

        __stcs(oL, l);
        __stcs(oR, make_float4(r0, r1, r2, r3));
        oL += HW4;
        oR += HW4;

        const int ni = w - d - 1;
        r3 = r2; r2 = r1; r1 = r0;
        r0 = (ni >= 0) ? YSM(ni) : 0.0f;
    }
}

extern "C" void kernel_launch(void* const* d_in, const int* in_sizes, int n_in,
                              void* d_out, int out_size)
{
    const float* x = (const float*)d_in[0];
    const float* y = (const float*)d_in[1];
    float* out = (float*)d_out;

    dim3 block(W4, 8);          // 480 threads
    dim3 grid(Hn, Cn, Bn);      // 80 x 32 x 2
    cost_volume_kernel<<<grid, block>>>(x, y, out);
}